// round 1
// baseline (speedup 1.0000x reference)
#include <cuda_runtime.h>

#define B_   4
#define T_   2048
#define C_   256
#define H_   8
#define HD_  32
#define C3_  768

// Scratch (module-load allocated, legal under the no-alloc rules)
__device__ float g_qkv[B_ * T_ * C3_];   // [B,T,3C]
__device__ float g_y  [B_ * T_ * C_];    // [B,T,C] attention output

// ----------------------------------------------------------------------------
// Tiled fp32 GEMM with fused bias: Cout[M,N] = A[M,K] @ W[K,N] + bias[N]
// BM=64, BN=64, BK=16, 256 threads, 4x4 register tile per thread.
// M,N,K are multiples of the tile sizes for all our shapes (no bounds checks).
// ----------------------------------------------------------------------------
__global__ __launch_bounds__(256, 4)
void gemm_bias_kernel(const float* __restrict__ A,
                      const float* __restrict__ W,
                      const float* __restrict__ bias,
                      float* __restrict__ Cout,
                      int M, int N, int K)
{
    __shared__ float As[16][65];   // [BK][BM+1] padded (transposed A tile)
    __shared__ float Ws[16][64];   // [BK][BN]

    const int tid = threadIdx.x;
    const int bm  = blockIdx.y * 64;
    const int bn  = blockIdx.x * 64;
    const int tx  = tid & 15;      // n direction
    const int ty  = tid >> 4;      // m direction

    // load mapping
    const int ar = tid >> 2;          // 0..63 : A row within tile
    const int ak = (tid & 3) * 4;     // 0,4,8,12 : A k-offset (float4)
    const int wr = tid >> 4;          // 0..15 : W row within tile
    const int wc = (tid & 15) * 4;    // 0..60 : W col offset (float4)

    float acc[4][4];
#pragma unroll
    for (int i = 0; i < 4; i++)
#pragma unroll
        for (int j = 0; j < 4; j++) acc[i][j] = 0.f;

    for (int k0 = 0; k0 < K; k0 += 16) {
        float4 a4 = *(const float4*)&A[(size_t)(bm + ar) * K + k0 + ak];
        float4 w4 = *(const float4*)&W[(size_t)(k0 + wr) * N + bn + wc];

        As[ak + 0][ar] = a4.x;
        As[ak + 1][ar] = a4.y;
        As[ak + 2][ar] = a4.z;
        As[ak + 3][ar] = a4.w;
        *(float4*)&Ws[wr][wc] = w4;
        __syncthreads();

#pragma unroll
        for (int kk = 0; kk < 16; kk++) {
            float ra[4];
            float4 rb = *(const float4*)&Ws[kk][tx * 4];
#pragma unroll
            for (int i = 0; i < 4; i++) ra[i] = As[kk][ty * 4 + i];
#pragma unroll
            for (int i = 0; i < 4; i++) {
                acc[i][0] += ra[i] * rb.x;
                acc[i][1] += ra[i] * rb.y;
                acc[i][2] += ra[i] * rb.z;
                acc[i][3] += ra[i] * rb.w;
            }
        }
        __syncthreads();
    }

    const int col = bn + tx * 4;
    const float4 bb = *(const float4*)&bias[col];
#pragma unroll
    for (int i = 0; i < 4; i++) {
        const int row = bm + ty * 4 + i;
        float4 out;
        out.x = acc[i][0] + bb.x;
        out.y = acc[i][1] + bb.y;
        out.z = acc[i][2] + bb.z;
        out.w = acc[i][3] + bb.w;
        *(float4*)&Cout[(size_t)row * N + col] = out;
    }
}

// ----------------------------------------------------------------------------
// Causal flash attention, fp32. One thread = one query row.
// grid = (T/128, B*H), block = 128 threads.
// Q and O accumulator in registers (HD=32 -> 8 float4 each).
// K/V staged in smem in tiles of 64 keys; online softmax.
// ----------------------------------------------------------------------------
__global__ __launch_bounds__(128, 8)
void attn_kernel()
{
    __shared__ float4 Ks[64 * 8];   // 64 keys x 32 dims
    __shared__ float4 Vs[64 * 8];

    const int tid = threadIdx.x;
    const int bh  = blockIdx.y;
    const int b   = bh / H_;
    const int h   = bh % H_;
    const int qi  = blockIdx.x * 128 + tid;
    const float scale = 0.17677669529663687f;   // 1/sqrt(32)

    // load this thread's query row into registers
    const float* qptr = g_qkv + (size_t)(b * T_ + qi) * C3_ + h * HD_;
    float4 q[8];
#pragma unroll
    for (int d = 0; d < 8; d++) q[d] = ((const float4*)qptr)[d];

    float4 o[8];
#pragma unroll
    for (int d = 0; d < 8; d++) o[d] = make_float4(0.f, 0.f, 0.f, 0.f);
    float m = -1e30f;
    float l = 0.f;

    const int nkt = 2 * blockIdx.x + 2;   // key tiles covering causal span of this q-block
    for (int kt = 0; kt < nkt; kt++) {
        const int base = kt * 64;
        __syncthreads();
        {
            const float* kg = g_qkv + (size_t)(b * T_ + base) * C3_ + C_ + h * HD_;
            const float* vg = kg + C_;
#pragma unroll
            for (int f = 0; f < 4; f++) {
                const int idx = tid + f * 128;     // 0..511
                const int row = idx >> 3;
                const int c4  = idx & 7;
                Ks[idx] = ((const float4*)(kg + (size_t)row * C3_))[c4];
                Vs[idx] = ((const float4*)(vg + (size_t)row * C3_))[c4];
            }
        }
        __syncthreads();

        int jmax = qi - base + 1;          // causal: keys <= qi
        if (jmax > 64) jmax = 64;
        for (int j = 0; j < jmax; j++) {
            const float4* kr = &Ks[j * 8];
            float s = 0.f;
#pragma unroll
            for (int d = 0; d < 8; d++) {
                float4 kk = kr[d];
                s += q[d].x * kk.x + q[d].y * kk.y + q[d].z * kk.z + q[d].w * kk.w;
            }
            s *= scale;
            if (s > m) {                    // rare after warmup: rescale
                const float corr = __expf(m - s);
                l *= corr;
#pragma unroll
                for (int d = 0; d < 8; d++) {
                    o[d].x *= corr; o[d].y *= corr; o[d].z *= corr; o[d].w *= corr;
                }
                m = s;
            }
            const float p = __expf(s - m);
            l += p;
            const float4* vr = &Vs[j * 8];
#pragma unroll
            for (int d = 0; d < 8; d++) {
                float4 vv = vr[d];
                o[d].x += p * vv.x; o[d].y += p * vv.y;
                o[d].z += p * vv.z; o[d].w += p * vv.w;
            }
        }
    }

    const float inv = 1.f / l;
    float* yo = g_y + (size_t)(b * T_ + qi) * C_ + h * HD_;
#pragma unroll
    for (int d = 0; d < 8; d++) {
        float4 v = make_float4(o[d].x * inv, o[d].y * inv, o[d].z * inv, o[d].w * inv);
        ((float4*)yo)[d] = v;
    }
}

// ----------------------------------------------------------------------------
extern "C" void kernel_launch(void* const* d_in, const int* in_sizes, int n_in,
                              void* d_out, int out_size)
{
    const float* x      = (const float*)d_in[0];
    const float* w_qkv  = (const float*)d_in[1];
    const float* b_qkv  = (const float*)d_in[2];
    const float* w_proj = (const float*)d_in[3];
    const float* b_proj = (const float*)d_in[4];
    float* out = (float*)d_out;

    float* qkv_ptr = nullptr;
    float* y_ptr   = nullptr;
    cudaGetSymbolAddress((void**)&qkv_ptr, g_qkv);
    cudaGetSymbolAddress((void**)&y_ptr,   g_y);

    const int M = B_ * T_;    // 8192

    // 1) QKV GEMM: [8192,256] @ [256,768] + bias
    {
        dim3 grid(C3_ / 64, M / 64);
        gemm_bias_kernel<<<grid, 256>>>(x, w_qkv, b_qkv, qkv_ptr, M, C3_, C_);
    }

    // 2) Causal attention
    {
        dim3 grid(T_ / 128, B_ * H_);
        attn_kernel<<<grid, 128>>>();
    }

    // 3) Projection GEMM: [8192,256] @ [256,256] + bias -> d_out
    {
        dim3 grid(C_ / 64, M / 64);
        gemm_bias_kernel<<<grid, 256>>>(y_ptr, w_proj, b_proj, out, M, C_, C_);
    }
}

// round 2
// speedup vs baseline: 2.0359x; 2.0359x over previous
#include <cuda_runtime.h>

#define B_   4
#define T_   2048
#define C_   256
#define H_   8
#define HD_  32
#define C3_  768

typedef unsigned long long u64;

// Scratch (module-load allocated, legal under the no-alloc rules)
__device__ float g_qkv[B_ * T_ * C3_];   // [B,T,3C]
__device__ float g_y  [B_ * T_ * C_];    // [B,T,C] attention output

// ---- packed f32x2 helpers (Blackwell) --------------------------------------
__device__ __forceinline__ u64 pk2(float lo, float hi) {
    u64 r; asm("mov.b64 %0, {%1, %2};" : "=l"(r) : "f"(lo), "f"(hi)); return r;
}
__device__ __forceinline__ void upk2(u64 v, float& lo, float& hi) {
    asm("mov.b64 {%0, %1}, %2;" : "=f"(lo), "=f"(hi) : "l"(v));
}
__device__ __forceinline__ u64 ffma2(u64 a, u64 b, u64 c) {
    u64 d; asm("fma.rn.f32x2 %0, %1, %2, %3;" : "=l"(d) : "l"(a), "l"(b), "l"(c));
    return d;
}
__device__ __forceinline__ u64 fmul2(u64 a, u64 b) {
    u64 d; asm("mul.rn.f32x2 %0, %1, %2;" : "=l"(d) : "l"(a), "l"(b));
    return d;
}

// ----------------------------------------------------------------------------
// Tiled fp32 GEMM with fused bias: Cout[M,N] = A[M,K] @ W[K,N] + bias[N]
// (unchanged from R1 — near its FFMA ceiling; will revisit with tensor cores)
// ----------------------------------------------------------------------------
__global__ __launch_bounds__(256, 4)
void gemm_bias_kernel(const float* __restrict__ A,
                      const float* __restrict__ W,
                      const float* __restrict__ bias,
                      float* __restrict__ Cout,
                      int M, int N, int K)
{
    __shared__ float As[16][65];
    __shared__ float Ws[16][64];

    const int tid = threadIdx.x;
    const int bm  = blockIdx.y * 64;
    const int bn  = blockIdx.x * 64;
    const int tx  = tid & 15;
    const int ty  = tid >> 4;

    const int ar = tid >> 2;
    const int ak = (tid & 3) * 4;
    const int wr = tid >> 4;
    const int wc = (tid & 15) * 4;

    float acc[4][4];
#pragma unroll
    for (int i = 0; i < 4; i++)
#pragma unroll
        for (int j = 0; j < 4; j++) acc[i][j] = 0.f;

    for (int k0 = 0; k0 < K; k0 += 16) {
        float4 a4 = *(const float4*)&A[(size_t)(bm + ar) * K + k0 + ak];
        float4 w4 = *(const float4*)&W[(size_t)(k0 + wr) * N + bn + wc];

        As[ak + 0][ar] = a4.x;
        As[ak + 1][ar] = a4.y;
        As[ak + 2][ar] = a4.z;
        As[ak + 3][ar] = a4.w;
        *(float4*)&Ws[wr][wc] = w4;
        __syncthreads();

#pragma unroll
        for (int kk = 0; kk < 16; kk++) {
            float ra[4];
            float4 rb = *(const float4*)&Ws[kk][tx * 4];
#pragma unroll
            for (int i = 0; i < 4; i++) ra[i] = As[kk][ty * 4 + i];
#pragma unroll
            for (int i = 0; i < 4; i++) {
                acc[i][0] += ra[i] * rb.x;
                acc[i][1] += ra[i] * rb.y;
                acc[i][2] += ra[i] * rb.z;
                acc[i][3] += ra[i] * rb.w;
            }
        }
        __syncthreads();
    }

    const int col = bn + tx * 4;
    const float4 bb = *(const float4*)&bias[col];
#pragma unroll
    for (int i = 0; i < 4; i++) {
        const int row = bm + ty * 4 + i;
        float4 out;
        out.x = acc[i][0] + bb.x;
        out.y = acc[i][1] + bb.y;
        out.z = acc[i][2] + bb.z;
        out.w = acc[i][3] + bb.w;
        *(float4*)&Cout[(size_t)row * N + col] = out;
    }
}

// ----------------------------------------------------------------------------
// Causal flash attention, fp32 math via packed f32x2.
// One thread = one query row; batches of 8 keys for ILP; online softmax with
// at most one rescale per batch. grid = (T/128, B*H), block = 128.
// ----------------------------------------------------------------------------
__global__ __launch_bounds__(128, 4)
void attn_kernel()
{
    __shared__ float4 Ks[64 * 8];   // 64 keys x 32 dims
    __shared__ float4 Vs[64 * 8];

    const int tid = threadIdx.x;
    const int bh  = blockIdx.y;
    const int b   = bh >> 3;
    const int h   = bh & 7;
    const int qi  = blockIdx.x * 128 + tid;
    const float scale = 0.17677669529663687f;   // 1/sqrt(32)

    // query row -> registers, pre-scaled, packed as 16 f32x2
    const float* qptr = g_qkv + (size_t)(b * T_ + qi) * C3_ + h * HD_;
    u64 q2[16];
#pragma unroll
    for (int d = 0; d < 8; d++) {
        float4 qq = ((const float4*)qptr)[d];
        q2[2 * d]     = pk2(qq.x * scale, qq.y * scale);
        q2[2 * d + 1] = pk2(qq.z * scale, qq.w * scale);
    }

    u64 o2[16];
#pragma unroll
    for (int i = 0; i < 16; i++) o2[i] = 0ull;   // (0.f, 0.f)
    float m = -1e30f;
    float l = 0.f;

    const int nkt = 2 * blockIdx.x + 2;
    for (int kt = 0; kt < nkt; kt++) {
        const int base = kt * 64;
        __syncthreads();
        {
            const float* kg = g_qkv + (size_t)(b * T_ + base) * C3_ + C_ + h * HD_;
            const float* vg = kg + C_;
#pragma unroll
            for (int f = 0; f < 4; f++) {
                const int idx = tid + f * 128;
                const int row = idx >> 3;
                const int c4  = idx & 7;
                Ks[idx] = ((const float4*)(kg + (size_t)row * C3_))[c4];
                Vs[idx] = ((const float4*)(vg + (size_t)row * C3_))[c4];
            }
        }
        __syncthreads();

        int jlim = qi - base + 1;          // causal span within tile
        if (jlim > 64) jlim = 64;

        for (int j0 = 0; j0 < jlim; j0 += 8) {
            // ---- scores for 8 keys (independent chains) ----
            float s[8];
#pragma unroll
            for (int u = 0; u < 8; u++) {
                const ulonglong2* kr = (const ulonglong2*)(Ks + (j0 + u) * 8);
                u64 a0 = 0ull, a1 = 0ull, a2 = 0ull, a3 = 0ull;
#pragma unroll
                for (int i = 0; i < 8; i += 2) {
                    ulonglong2 k0 = kr[i];
                    ulonglong2 k1 = kr[i + 1];
                    a0 = ffma2(q2[2 * i],     k0.x, a0);
                    a1 = ffma2(q2[2 * i + 1], k0.y, a1);
                    a2 = ffma2(q2[2 * i + 2], k1.x, a2);
                    a3 = ffma2(q2[2 * i + 3], k1.y, a3);
                }
                float x0, x1, y0, y1, z0, z1, w0, w1;
                upk2(a0, x0, x1); upk2(a1, y0, y1);
                upk2(a2, z0, z1); upk2(a3, w0, w1);
                s[u] = ((x0 + x1) + (y0 + y1)) + ((z0 + z1) + (w0 + w1));
            }
            // causal mask within the batch
#pragma unroll
            for (int u = 0; u < 8; u++)
                if (j0 + u >= jlim) s[u] = -1e30f;

            // ---- online softmax, one rescale per batch max ----
            float bm = s[0];
#pragma unroll
            for (int u = 1; u < 8; u++) bm = fmaxf(bm, s[u]);
            if (bm > m) {
                const float corr = __expf(m - bm);
                l *= corr;
                const u64 c2 = pk2(corr, corr);
#pragma unroll
                for (int i = 0; i < 16; i++) o2[i] = fmul2(o2[i], c2);
                m = bm;
            }
            float p[8];
#pragma unroll
            for (int u = 0; u < 8; u++) { p[u] = __expf(s[u] - m); l += p[u]; }

            // ---- accumulate P @ V ----
#pragma unroll
            for (int u = 0; u < 8; u++) {
                const ulonglong2* vr = (const ulonglong2*)(Vs + (j0 + u) * 8);
                const u64 pp = pk2(p[u], p[u]);
#pragma unroll
                for (int i = 0; i < 8; i++) {
                    ulonglong2 vv = vr[i];
                    o2[2 * i]     = ffma2(pp, vv.x, o2[2 * i]);
                    o2[2 * i + 1] = ffma2(pp, vv.y, o2[2 * i + 1]);
                }
            }
        }
    }

    const float inv = 1.f / l;
    const u64 iv = pk2(inv, inv);
    float* yo = g_y + (size_t)(b * T_ + qi) * C_ + h * HD_;
#pragma unroll
    for (int i = 0; i < 16; i++) {
        u64 r = fmul2(o2[i], iv);
        float lo, hi; upk2(r, lo, hi);
        ((float2*)yo)[i] = make_float2(lo, hi);
    }
}

// ----------------------------------------------------------------------------
extern "C" void kernel_launch(void* const* d_in, const int* in_sizes, int n_in,
                              void* d_out, int out_size)
{
    const float* x      = (const float*)d_in[0];
    const float* w_qkv  = (const float*)d_in[1];
    const float* b_qkv  = (const float*)d_in[2];
    const float* w_proj = (const float*)d_in[3];
    const float* b_proj = (const float*)d_in[4];
    float* out = (float*)d_out;

    float* qkv_ptr = nullptr;
    float* y_ptr   = nullptr;
    cudaGetSymbolAddress((void**)&qkv_ptr, g_qkv);
    cudaGetSymbolAddress((void**)&y_ptr,   g_y);

    const int M = B_ * T_;    // 8192

    // 1) QKV GEMM: [8192,256] @ [256,768] + bias
    {
        dim3 grid(C3_ / 64, M / 64);
        gemm_bias_kernel<<<grid, 256>>>(x, w_qkv, b_qkv, qkv_ptr, M, C3_, C_);
    }

    // 2) Causal attention
    {
        dim3 grid(T_ / 128, B_ * H_);
        attn_kernel<<<grid, 128>>>();
    }

    // 3) Projection GEMM: [8192,256] @ [256,256] + bias -> d_out
    {
        dim3 grid(C_ / 64, M / 64);
        gemm_bias_kernel<<<grid, 256>>>(y_ptr, w_proj, b_proj, out, M, C_, C_);
    }
}

// round 3
// speedup vs baseline: 4.5269x; 2.2235x over previous
#include <cuda_runtime.h>
#include <cstdint>

#define B_   4
#define T_   2048
#define C_   256
#define H_   8
#define HD_  32
#define C3_  768

// Scratch (module-load allocated, legal under the no-alloc rules)
__device__ float g_qkv[B_ * T_ * C3_];   // [B,T,3C]
__device__ float g_y  [B_ * T_ * C_];    // [B,T,C] attention output

// ---- helpers ---------------------------------------------------------------
__device__ __forceinline__ uint32_t cvt_tf32(float x) {
    uint32_t r; asm("cvt.rna.tf32.f32 %0, %1;" : "=r"(r) : "f"(x)); return r;
}
__device__ __forceinline__ float ex2f(float x) {
    float y; asm("ex2.approx.f32 %0, %1;" : "=f"(y) : "f"(x)); return y;
}
__device__ __forceinline__ void mma_tf32(float& c0, float& c1, float& c2, float& c3,
                                         uint32_t a0, uint32_t a1, uint32_t a2, uint32_t a3,
                                         uint32_t b0, uint32_t b1) {
    asm volatile("mma.sync.aligned.m16n8k8.row.col.f32.tf32.tf32.f32 "
                 "{%0,%1,%2,%3}, {%4,%5,%6,%7}, {%8,%9}, {%0,%1,%2,%3};"
                 : "+f"(c0), "+f"(c1), "+f"(c2), "+f"(c3)
                 : "r"(a0), "r"(a1), "r"(a2), "r"(a3), "r"(b0), "r"(b1));
}

// ----------------------------------------------------------------------------
// Tiled fp32 GEMM with fused bias (unchanged — near its FFMA ceiling; tensor-
// core conversion is next round once the mma path is validated by attention).
// ----------------------------------------------------------------------------
__global__ __launch_bounds__(256, 4)
void gemm_bias_kernel(const float* __restrict__ A,
                      const float* __restrict__ W,
                      const float* __restrict__ bias,
                      float* __restrict__ Cout,
                      int M, int N, int K)
{
    __shared__ float As[16][65];
    __shared__ float Ws[16][64];

    const int tid = threadIdx.x;
    const int bm  = blockIdx.y * 64;
    const int bn  = blockIdx.x * 64;
    const int tx  = tid & 15;
    const int ty  = tid >> 4;

    const int ar = tid >> 2;
    const int ak = (tid & 3) * 4;
    const int wr = tid >> 4;
    const int wc = (tid & 15) * 4;

    float acc[4][4];
#pragma unroll
    for (int i = 0; i < 4; i++)
#pragma unroll
        for (int j = 0; j < 4; j++) acc[i][j] = 0.f;

    for (int k0 = 0; k0 < K; k0 += 16) {
        float4 a4 = *(const float4*)&A[(size_t)(bm + ar) * K + k0 + ak];
        float4 w4 = *(const float4*)&W[(size_t)(k0 + wr) * N + bn + wc];

        As[ak + 0][ar] = a4.x;
        As[ak + 1][ar] = a4.y;
        As[ak + 2][ar] = a4.z;
        As[ak + 3][ar] = a4.w;
        *(float4*)&Ws[wr][wc] = w4;
        __syncthreads();

#pragma unroll
        for (int kk = 0; kk < 16; kk++) {
            float ra[4];
            float4 rb = *(const float4*)&Ws[kk][tx * 4];
#pragma unroll
            for (int i = 0; i < 4; i++) ra[i] = As[kk][ty * 4 + i];
#pragma unroll
            for (int i = 0; i < 4; i++) {
                acc[i][0] += ra[i] * rb.x;
                acc[i][1] += ra[i] * rb.y;
                acc[i][2] += ra[i] * rb.z;
                acc[i][3] += ra[i] * rb.w;
            }
        }
        __syncthreads();
    }

    const int col = bn + tx * 4;
    const float4 bb = *(const float4*)&bias[col];
#pragma unroll
    for (int i = 0; i < 4; i++) {
        const int row = bm + ty * 4 + i;
        float4 out;
        out.x = acc[i][0] + bb.x;
        out.y = acc[i][1] + bb.y;
        out.z = acc[i][2] + bb.z;
        out.w = acc[i][3] + bb.w;
        *(float4*)&Cout[(size_t)row * N + col] = out;
    }
}

// ----------------------------------------------------------------------------
// Causal flash attention, tf32 mma.sync tensor cores.
// Block = 128 threads (4 warps), 64 query rows per block (16 per warp),
// key tiles of 64. S = Q·K^T via m16n8k8, online softmax on fragments,
// P -> smem -> A-fragments, O += P·V via m16n8k8.
// grid = (T/64, B*H).
// ----------------------------------------------------------------------------
#define KSTRIDE 36   // 32 + 4 pad: bank = (4*row + col) % 32 -> conflict-free frags
#define PSTRIDE 68   // 64 + 4 pad

__global__ __launch_bounds__(128, 2)
void attn_mma_kernel()
{
    __shared__ uint32_t Qs[64 * KSTRIDE];
    __shared__ uint32_t Ks[64 * KSTRIDE];
    __shared__ uint32_t Vs[64 * KSTRIDE];
    __shared__ uint32_t Ps[4][16 * PSTRIDE];

    const int tid  = threadIdx.x;
    const int wid  = tid >> 5;
    const int lane = tid & 31;
    const int g    = lane >> 2;      // group id (row within fragment)
    const int tg   = lane & 3;       // thread in group

    const int qt = gridDim.x - 1 - blockIdx.x;   // heavy (long-span) blocks first
    const int q0 = qt * 64;
    const int bh = blockIdx.y;
    const int b  = bh >> 3;
    const int h  = bh & 7;

    // softmax scale with log2(e) folded in (we exponentiate base-2)
    const float qscale = 0.17677669529663687f * 1.4426950408889634f;

    // ---- load Q tile (64 x 32): scale, cvt->tf32, smem stride 36 ----
    {
        const float* qg = g_qkv + (size_t)(b * T_ + q0) * C3_ + h * HD_;
#pragma unroll
        for (int f = 0; f < 4; f++) {
            int idx = tid + f * 128;
            int row = idx >> 3, c4 = idx & 7;
            float4 v = ((const float4*)(qg + (size_t)row * C3_))[c4];
            uint4 o;
            o.x = cvt_tf32(v.x * qscale); o.y = cvt_tf32(v.y * qscale);
            o.z = cvt_tf32(v.z * qscale); o.w = cvt_tf32(v.w * qscale);
            *(uint4*)&Qs[row * KSTRIDE + c4 * 4] = o;
        }
    }
    __syncthreads();

    // ---- Q fragments: 4 k-steps x 4 regs ----
    uint32_t qa[4][4];
    {
        const int r0 = wid * 16 + g;
#pragma unroll
        for (int kk = 0; kk < 4; kk++) {
            qa[kk][0] = Qs[r0 * KSTRIDE + kk * 8 + tg];
            qa[kk][1] = Qs[(r0 + 8) * KSTRIDE + kk * 8 + tg];
            qa[kk][2] = Qs[r0 * KSTRIDE + kk * 8 + tg + 4];
            qa[kk][3] = Qs[(r0 + 8) * KSTRIDE + kk * 8 + tg + 4];
        }
    }

    float o_[4][4];
#pragma unroll
    for (int nt = 0; nt < 4; nt++)
#pragma unroll
        for (int c = 0; c < 4; c++) o_[nt][c] = 0.f;
    float m0 = -1e30f, m1 = -1e30f, l0 = 0.f, l1 = 0.f;

    const int nkt = qt + 1;
    for (int kt = 0; kt < nkt; kt++) {
        __syncthreads();
        // ---- load K, V tiles (64 x 32 each), cvt->tf32 ----
        {
            const float* kg = g_qkv + (size_t)(b * T_ + kt * 64) * C3_ + C_ + h * HD_;
            const float* vg = kg + C_;
#pragma unroll
            for (int f = 0; f < 4; f++) {
                int idx = tid + f * 128;
                int row = idx >> 3, c4 = idx & 7;
                float4 kv = ((const float4*)(kg + (size_t)row * C3_))[c4];
                float4 vv = ((const float4*)(vg + (size_t)row * C3_))[c4];
                uint4 ok, ov;
                ok.x = cvt_tf32(kv.x); ok.y = cvt_tf32(kv.y);
                ok.z = cvt_tf32(kv.z); ok.w = cvt_tf32(kv.w);
                ov.x = cvt_tf32(vv.x); ov.y = cvt_tf32(vv.y);
                ov.z = cvt_tf32(vv.z); ov.w = cvt_tf32(vv.w);
                *(uint4*)&Ks[row * KSTRIDE + c4 * 4] = ok;
                *(uint4*)&Vs[row * KSTRIDE + c4 * 4] = ov;
            }
        }
        __syncthreads();

        // ---- S = Q K^T : 8 n-tiles (64 keys) x 4 k-steps ----
        float s[8][4];
#pragma unroll
        for (int nt = 0; nt < 8; nt++)
#pragma unroll
            for (int c = 0; c < 4; c++) s[nt][c] = 0.f;

#pragma unroll
        for (int kk = 0; kk < 4; kk++) {
#pragma unroll
            for (int nt = 0; nt < 8; nt++) {
                uint32_t b0 = Ks[(nt * 8 + g) * KSTRIDE + kk * 8 + tg];
                uint32_t b1 = Ks[(nt * 8 + g) * KSTRIDE + kk * 8 + tg + 4];
                mma_tf32(s[nt][0], s[nt][1], s[nt][2], s[nt][3],
                         qa[kk][0], qa[kk][1], qa[kk][2], qa[kk][3], b0, b1);
            }
        }

        // ---- causal mask on the diagonal tile (key base == q0) ----
        if (kt == nkt - 1) {
            const int r0 = wid * 16 + g;
#pragma unroll
            for (int nt = 0; nt < 8; nt++) {
                const int col0 = nt * 8 + 2 * tg;
                if (col0     > r0)     s[nt][0] = -1e30f;
                if (col0 + 1 > r0)     s[nt][1] = -1e30f;
                if (col0     > r0 + 8) s[nt][2] = -1e30f;
                if (col0 + 1 > r0 + 8) s[nt][3] = -1e30f;
            }
        }

        // ---- online softmax on fragments ----
        float tm0 = s[0][0], tm1 = s[0][2];
#pragma unroll
        for (int nt = 0; nt < 8; nt++) {
            tm0 = fmaxf(tm0, fmaxf(s[nt][0], s[nt][1]));
            tm1 = fmaxf(tm1, fmaxf(s[nt][2], s[nt][3]));
        }
        tm0 = fmaxf(tm0, __shfl_xor_sync(0xffffffffu, tm0, 1));
        tm0 = fmaxf(tm0, __shfl_xor_sync(0xffffffffu, tm0, 2));
        tm1 = fmaxf(tm1, __shfl_xor_sync(0xffffffffu, tm1, 1));
        tm1 = fmaxf(tm1, __shfl_xor_sync(0xffffffffu, tm1, 2));

        const float nm0 = fmaxf(m0, tm0);
        const float nm1 = fmaxf(m1, tm1);
        const float corr0 = ex2f(m0 - nm0);
        const float corr1 = ex2f(m1 - nm1);
        m0 = nm0; m1 = nm1;
        l0 *= corr0; l1 *= corr1;
#pragma unroll
        for (int nt = 0; nt < 4; nt++) {
            o_[nt][0] *= corr0; o_[nt][1] *= corr0;
            o_[nt][2] *= corr1; o_[nt][3] *= corr1;
        }

        // ---- P = exp2(S - m), accumulate l, spill P to per-warp smem ----
        uint32_t* pw = Ps[wid];
#pragma unroll
        for (int nt = 0; nt < 8; nt++) {
            float p0 = ex2f(s[nt][0] - m0);
            float p1 = ex2f(s[nt][1] - m0);
            float p2 = ex2f(s[nt][2] - m1);
            float p3 = ex2f(s[nt][3] - m1);
            l0 += p0 + p1;
            l1 += p2 + p3;
            uint2 w0; w0.x = cvt_tf32(p0); w0.y = cvt_tf32(p1);
            uint2 w1; w1.x = cvt_tf32(p2); w1.y = cvt_tf32(p3);
            *(uint2*)&pw[g * PSTRIDE + nt * 8 + 2 * tg]       = w0;
            *(uint2*)&pw[(g + 8) * PSTRIDE + nt * 8 + 2 * tg] = w1;
        }
        __syncwarp();

        // ---- O += P V : 8 k-steps (64 keys) x 4 n-tiles (32 hd) ----
#pragma unroll
        for (int kk2 = 0; kk2 < 8; kk2++) {
            uint32_t a0 = pw[g * PSTRIDE + kk2 * 8 + tg];
            uint32_t a1 = pw[(g + 8) * PSTRIDE + kk2 * 8 + tg];
            uint32_t a2 = pw[g * PSTRIDE + kk2 * 8 + tg + 4];
            uint32_t a3 = pw[(g + 8) * PSTRIDE + kk2 * 8 + tg + 4];
#pragma unroll
            for (int nt = 0; nt < 4; nt++) {
                uint32_t b0 = Vs[(kk2 * 8 + tg) * KSTRIDE + nt * 8 + g];
                uint32_t b1 = Vs[(kk2 * 8 + tg + 4) * KSTRIDE + nt * 8 + g];
                mma_tf32(o_[nt][0], o_[nt][1], o_[nt][2], o_[nt][3],
                         a0, a1, a2, a3, b0, b1);
            }
        }
        __syncwarp();   // P reads complete before any next-tile reuse
    }

    // ---- finalize: row sums across the 4-lane group, normalize, store ----
    l0 += __shfl_xor_sync(0xffffffffu, l0, 1);
    l0 += __shfl_xor_sync(0xffffffffu, l0, 2);
    l1 += __shfl_xor_sync(0xffffffffu, l1, 1);
    l1 += __shfl_xor_sync(0xffffffffu, l1, 2);
    const float i0 = 1.f / l0;
    const float i1 = 1.f / l1;

    const int qrow0 = q0 + wid * 16 + g;
    float* y0 = g_y + (size_t)(b * T_ + qrow0) * C_ + h * HD_;
    float* y1 = y0 + (size_t)8 * C_;
#pragma unroll
    for (int nt = 0; nt < 4; nt++) {
        float2 r0; r0.x = o_[nt][0] * i0; r0.y = o_[nt][1] * i0;
        float2 r1; r1.x = o_[nt][2] * i1; r1.y = o_[nt][3] * i1;
        *(float2*)&y0[nt * 8 + 2 * tg] = r0;
        *(float2*)&y1[nt * 8 + 2 * tg] = r1;
    }
}

// ----------------------------------------------------------------------------
extern "C" void kernel_launch(void* const* d_in, const int* in_sizes, int n_in,
                              void* d_out, int out_size)
{
    const float* x      = (const float*)d_in[0];
    const float* w_qkv  = (const float*)d_in[1];
    const float* b_qkv  = (const float*)d_in[2];
    const float* w_proj = (const float*)d_in[3];
    const float* b_proj = (const float*)d_in[4];
    float* out = (float*)d_out;

    float* qkv_ptr = nullptr;
    float* y_ptr   = nullptr;
    cudaGetSymbolAddress((void**)&qkv_ptr, g_qkv);
    cudaGetSymbolAddress((void**)&y_ptr,   g_y);

    const int M = B_ * T_;    // 8192

    // 1) QKV GEMM: [8192,256] @ [256,768] + bias
    {
        dim3 grid(C3_ / 64, M / 64);
        gemm_bias_kernel<<<grid, 256>>>(x, w_qkv, b_qkv, qkv_ptr, M, C3_, C_);
    }

    // 2) Causal attention (tensor cores)
    {
        dim3 grid(T_ / 64, B_ * H_);
        attn_mma_kernel<<<grid, 128>>>();
    }

    // 3) Projection GEMM: [8192,256] @ [256,256] + bias -> d_out
    {
        dim3 grid(C_ / 64, M / 64);
        gemm_bias_kernel<<<grid, 256>>>(y_ptr, w_proj, b_proj, out, M, C_, C_);
    }
}

// round 4
// speedup vs baseline: 5.3998x; 1.1928x over previous
#include <cuda_runtime.h>
#include <cstdint>

#define B_   4
#define T_   2048
#define C_   256
#define H_   8
#define HD_  32
#define C3_  768

// Scratch (module-load allocated, legal under the no-alloc rules)
__device__ float g_qkv[B_ * T_ * C3_];   // [B,T,3C]
__device__ float g_y  [B_ * T_ * C_];    // [B,T,C] attention output

// ---- helpers ---------------------------------------------------------------
__device__ __forceinline__ uint32_t cvt_tf32(float x) {
    uint32_t r; asm("cvt.rna.tf32.f32 %0, %1;" : "=r"(r) : "f"(x)); return r;
}
__device__ __forceinline__ void split_tf32(float x, uint32_t& hi, uint32_t& lo) {
    hi = cvt_tf32(x);
    lo = cvt_tf32(x - __uint_as_float(hi));
}
__device__ __forceinline__ float ex2f(float x) {
    float y; asm("ex2.approx.f32 %0, %1;" : "=f"(y) : "f"(x)); return y;
}
__device__ __forceinline__ void mma_tf32(float& c0, float& c1, float& c2, float& c3,
                                         uint32_t a0, uint32_t a1, uint32_t a2, uint32_t a3,
                                         uint32_t b0, uint32_t b1) {
    asm volatile("mma.sync.aligned.m16n8k8.row.col.f32.tf32.tf32.f32 "
                 "{%0,%1,%2,%3}, {%4,%5,%6,%7}, {%8,%9}, {%0,%1,%2,%3};"
                 : "+f"(c0), "+f"(c1), "+f"(c2), "+f"(c3)
                 : "r"(a0), "r"(a1), "r"(a2), "r"(a3), "r"(b0), "r"(b1));
}
__device__ __forceinline__ void cp_async16(uint32_t saddr, const void* gptr) {
    asm volatile("cp.async.cg.shared.global [%0], [%1], 16;" :: "r"(saddr), "l"(gptr));
}
__device__ __forceinline__ void cp_commit() {
    asm volatile("cp.async.commit_group;");
}
template <int N>
__device__ __forceinline__ void cp_wait() {
    asm volatile("cp.async.wait_group %0;" :: "n"(N));
}

// ----------------------------------------------------------------------------
// Tensor-core GEMM with fused bias, 3xTF32 split precision (~fp32 accuracy):
//   Cout[M,N] = A[M,K] @ W[K,N] + bias[N]
// BM=128, BN=64, BK=16, 256 threads (8 warps: 4m x 2n, 32x32 warp tile).
// Raw fp32 tiles staged via cp.async double-buffer; hi/lo split at frag read.
// A smem stride 36 (banks 4g+tg, conflict-free), W stride 72 (banks 8tg+g).
// ----------------------------------------------------------------------------
#define ASTRIDE 36
#define WSTRIDE 72

__global__ __launch_bounds__(256, 2)
void gemm_mma_kernel(const float* __restrict__ A,
                     const float* __restrict__ W,
                     const float* __restrict__ bias,
                     float* __restrict__ Cout,
                     int M, int N, int K)
{
    __shared__ float As[2][128 * ASTRIDE];   // 36864 B
    __shared__ float Ws[2][16 * WSTRIDE];    //  9216 B

    const int tid  = threadIdx.x;
    const int wid  = tid >> 5;
    const int lane = tid & 31;
    const int g    = lane >> 2;
    const int tg   = lane & 3;
    const int wm   = wid & 3;      // m warp: 0..3 (32 rows each)
    const int wn   = wid >> 2;     // n warp: 0..1 (32 cols each)

    const int bm = blockIdx.y * 128;
    const int bn = blockIdx.x * 64;

    // gmem->smem load mapping
    const int a_row = tid >> 2;          // 0..63 (two passes: +0, +64)
    const int a_k4  = (tid & 3) * 4;
    const int w_row = tid >> 4;          // 0..15
    const int w_c4  = (tid & 15) * 4;

    const uint32_t sA0 = (uint32_t)__cvta_generic_to_shared(&As[0][0]);
    const uint32_t sA1 = (uint32_t)__cvta_generic_to_shared(&As[1][0]);
    const uint32_t sW0 = (uint32_t)__cvta_generic_to_shared(&Ws[0][0]);
    const uint32_t sW1 = (uint32_t)__cvta_generic_to_shared(&Ws[1][0]);

    const int nChunks = K >> 4;

    // prefetch one chunk into buffer `buf`
    auto prefetch = [&](int buf, int c) {
        const uint32_t sa = buf ? sA1 : sA0;
        const uint32_t sw = buf ? sW1 : sW0;
        const int k0 = c * 16;
        cp_async16(sa + (uint32_t)(a_row * ASTRIDE + a_k4) * 4,
                   &A[(size_t)(bm + a_row) * K + k0 + a_k4]);
        cp_async16(sa + (uint32_t)((a_row + 64) * ASTRIDE + a_k4) * 4,
                   &A[(size_t)(bm + a_row + 64) * K + k0 + a_k4]);
        cp_async16(sw + (uint32_t)(w_row * WSTRIDE + w_c4) * 4,
                   &W[(size_t)(k0 + w_row) * N + bn + w_c4]);
    };

    float acc[2][4][4];
#pragma unroll
    for (int r = 0; r < 2; r++)
#pragma unroll
        for (int c = 0; c < 4; c++)
#pragma unroll
            for (int i = 0; i < 4; i++) acc[r][c][i] = 0.f;

    prefetch(0, 0);
    cp_commit();

    for (int ch = 0; ch < nChunks; ch++) {
        if (ch + 1 < nChunks) {
            prefetch((ch + 1) & 1, ch + 1);
            cp_commit();
            cp_wait<1>();
        } else {
            cp_wait<0>();
        }
        __syncthreads();

        const float* Ab = As[ch & 1];
        const float* Wb = Ws[ch & 1];

#pragma unroll
        for (int kk = 0; kk < 2; kk++) {
            // ---- A fragments (2 m-tiles), hi/lo split ----
            uint32_t ah[2][4], al[2][4];
#pragma unroll
            for (int r = 0; r < 2; r++) {
                const int row0 = wm * 32 + r * 16;
                float x0 = Ab[(row0 + g)     * ASTRIDE + kk * 8 + tg];
                float x1 = Ab[(row0 + g + 8) * ASTRIDE + kk * 8 + tg];
                float x2 = Ab[(row0 + g)     * ASTRIDE + kk * 8 + tg + 4];
                float x3 = Ab[(row0 + g + 8) * ASTRIDE + kk * 8 + tg + 4];
                split_tf32(x0, ah[r][0], al[r][0]);
                split_tf32(x1, ah[r][1], al[r][1]);
                split_tf32(x2, ah[r][2], al[r][2]);
                split_tf32(x3, ah[r][3], al[r][3]);
            }
            // ---- B fragments (4 n-tiles), hi/lo split ----
            uint32_t bh[4][2], bl[4][2];
#pragma unroll
            for (int c = 0; c < 4; c++) {
                const int col = wn * 32 + c * 8 + g;
                float y0 = Wb[(kk * 8 + tg)     * WSTRIDE + col];
                float y1 = Wb[(kk * 8 + tg + 4) * WSTRIDE + col];
                split_tf32(y0, bh[c][0], bl[c][0]);
                split_tf32(y1, bh[c][1], bl[c][1]);
            }
            // ---- 3-term mma: hi*hi + hi*lo + lo*hi ----
#pragma unroll
            for (int r = 0; r < 2; r++) {
#pragma unroll
                for (int c = 0; c < 4; c++) {
                    mma_tf32(acc[r][c][0], acc[r][c][1], acc[r][c][2], acc[r][c][3],
                             ah[r][0], ah[r][1], ah[r][2], ah[r][3], bh[c][0], bh[c][1]);
                    mma_tf32(acc[r][c][0], acc[r][c][1], acc[r][c][2], acc[r][c][3],
                             ah[r][0], ah[r][1], ah[r][2], ah[r][3], bl[c][0], bl[c][1]);
                    mma_tf32(acc[r][c][0], acc[r][c][1], acc[r][c][2], acc[r][c][3],
                             al[r][0], al[r][1], al[r][2], al[r][3], bh[c][0], bh[c][1]);
                }
            }
        }
        __syncthreads();
    }

    // ---- epilogue: bias + store ----
#pragma unroll
    for (int r = 0; r < 2; r++) {
        const int row0 = bm + wm * 32 + r * 16 + g;
#pragma unroll
        for (int c = 0; c < 4; c++) {
            const int col = bn + wn * 32 + c * 8 + 2 * tg;
            const float2 bb = *(const float2*)&bias[col];
            float2 v0, v1;
            v0.x = acc[r][c][0] + bb.x; v0.y = acc[r][c][1] + bb.y;
            v1.x = acc[r][c][2] + bb.x; v1.y = acc[r][c][3] + bb.y;
            *(float2*)&Cout[(size_t)row0 * N + col]       = v0;
            *(float2*)&Cout[(size_t)(row0 + 8) * N + col] = v1;
        }
    }
}

// ----------------------------------------------------------------------------
// Causal flash attention, tf32 mma.sync tensor cores. (unchanged from R3)
// ----------------------------------------------------------------------------
#define KSTRIDE 36
#define PSTRIDE 68

__global__ __launch_bounds__(128, 2)
void attn_mma_kernel()
{
    __shared__ uint32_t Qs[64 * KSTRIDE];
    __shared__ uint32_t Ks[64 * KSTRIDE];
    __shared__ uint32_t Vs[64 * KSTRIDE];
    __shared__ uint32_t Ps[4][16 * PSTRIDE];

    const int tid  = threadIdx.x;
    const int wid  = tid >> 5;
    const int lane = tid & 31;
    const int g    = lane >> 2;
    const int tg   = lane & 3;

    const int qt = gridDim.x - 1 - blockIdx.x;
    const int q0 = qt * 64;
    const int bh = blockIdx.y;
    const int b  = bh >> 3;
    const int h  = bh & 7;

    const float qscale = 0.17677669529663687f * 1.4426950408889634f;

    {
        const float* qg = g_qkv + (size_t)(b * T_ + q0) * C3_ + h * HD_;
#pragma unroll
        for (int f = 0; f < 4; f++) {
            int idx = tid + f * 128;
            int row = idx >> 3, c4 = idx & 7;
            float4 v = ((const float4*)(qg + (size_t)row * C3_))[c4];
            uint4 o;
            o.x = cvt_tf32(v.x * qscale); o.y = cvt_tf32(v.y * qscale);
            o.z = cvt_tf32(v.z * qscale); o.w = cvt_tf32(v.w * qscale);
            *(uint4*)&Qs[row * KSTRIDE + c4 * 4] = o;
        }
    }
    __syncthreads();

    uint32_t qa[4][4];
    {
        const int r0 = wid * 16 + g;
#pragma unroll
        for (int kk = 0; kk < 4; kk++) {
            qa[kk][0] = Qs[r0 * KSTRIDE + kk * 8 + tg];
            qa[kk][1] = Qs[(r0 + 8) * KSTRIDE + kk * 8 + tg];
            qa[kk][2] = Qs[r0 * KSTRIDE + kk * 8 + tg + 4];
            qa[kk][3] = Qs[(r0 + 8) * KSTRIDE + kk * 8 + tg + 4];
        }
    }

    float o_[4][4];
#pragma unroll
    for (int nt = 0; nt < 4; nt++)
#pragma unroll
        for (int c = 0; c < 4; c++) o_[nt][c] = 0.f;
    float m0 = -1e30f, m1 = -1e30f, l0 = 0.f, l1 = 0.f;

    const int nkt = qt + 1;
    for (int kt = 0; kt < nkt; kt++) {
        __syncthreads();
        {
            const float* kg = g_qkv + (size_t)(b * T_ + kt * 64) * C3_ + C_ + h * HD_;
            const float* vg = kg + C_;
#pragma unroll
            for (int f = 0; f < 4; f++) {
                int idx = tid + f * 128;
                int row = idx >> 3, c4 = idx & 7;
                float4 kv = ((const float4*)(kg + (size_t)row * C3_))[c4];
                float4 vv = ((const float4*)(vg + (size_t)row * C3_))[c4];
                uint4 ok, ov;
                ok.x = cvt_tf32(kv.x); ok.y = cvt_tf32(kv.y);
                ok.z = cvt_tf32(kv.z); ok.w = cvt_tf32(kv.w);
                ov.x = cvt_tf32(vv.x); ov.y = cvt_tf32(vv.y);
                ov.z = cvt_tf32(vv.z); ov.w = cvt_tf32(vv.w);
                *(uint4*)&Ks[row * KSTRIDE + c4 * 4] = ok;
                *(uint4*)&Vs[row * KSTRIDE + c4 * 4] = ov;
            }
        }
        __syncthreads();

        float s[8][4];
#pragma unroll
        for (int nt = 0; nt < 8; nt++)
#pragma unroll
            for (int c = 0; c < 4; c++) s[nt][c] = 0.f;

#pragma unroll
        for (int kk = 0; kk < 4; kk++) {
#pragma unroll
            for (int nt = 0; nt < 8; nt++) {
                uint32_t b0 = Ks[(nt * 8 + g) * KSTRIDE + kk * 8 + tg];
                uint32_t b1 = Ks[(nt * 8 + g) * KSTRIDE + kk * 8 + tg + 4];
                mma_tf32(s[nt][0], s[nt][1], s[nt][2], s[nt][3],
                         qa[kk][0], qa[kk][1], qa[kk][2], qa[kk][3], b0, b1);
            }
        }

        if (kt == nkt - 1) {
            const int r0 = wid * 16 + g;
#pragma unroll
            for (int nt = 0; nt < 8; nt++) {
                const int col0 = nt * 8 + 2 * tg;
                if (col0     > r0)     s[nt][0] = -1e30f;
                if (col0 + 1 > r0)     s[nt][1] = -1e30f;
                if (col0     > r0 + 8) s[nt][2] = -1e30f;
                if (col0 + 1 > r0 + 8) s[nt][3] = -1e30f;
            }
        }

        float tm0 = s[0][0], tm1 = s[0][2];
#pragma unroll
        for (int nt = 0; nt < 8; nt++) {
            tm0 = fmaxf(tm0, fmaxf(s[nt][0], s[nt][1]));
            tm1 = fmaxf(tm1, fmaxf(s[nt][2], s[nt][3]));
        }
        tm0 = fmaxf(tm0, __shfl_xor_sync(0xffffffffu, tm0, 1));
        tm0 = fmaxf(tm0, __shfl_xor_sync(0xffffffffu, tm0, 2));
        tm1 = fmaxf(tm1, __shfl_xor_sync(0xffffffffu, tm1, 1));
        tm1 = fmaxf(tm1, __shfl_xor_sync(0xffffffffu, tm1, 2));

        const float nm0 = fmaxf(m0, tm0);
        const float nm1 = fmaxf(m1, tm1);
        const float corr0 = ex2f(m0 - nm0);
        const float corr1 = ex2f(m1 - nm1);
        m0 = nm0; m1 = nm1;
        l0 *= corr0; l1 *= corr1;
#pragma unroll
        for (int nt = 0; nt < 4; nt++) {
            o_[nt][0] *= corr0; o_[nt][1] *= corr0;
            o_[nt][2] *= corr1; o_[nt][3] *= corr1;
        }

        uint32_t* pw = Ps[wid];
#pragma unroll
        for (int nt = 0; nt < 8; nt++) {
            float p0 = ex2f(s[nt][0] - m0);
            float p1 = ex2f(s[nt][1] - m0);
            float p2 = ex2f(s[nt][2] - m1);
            float p3 = ex2f(s[nt][3] - m1);
            l0 += p0 + p1;
            l1 += p2 + p3;
            uint2 w0; w0.x = cvt_tf32(p0); w0.y = cvt_tf32(p1);
            uint2 w1; w1.x = cvt_tf32(p2); w1.y = cvt_tf32(p3);
            *(uint2*)&pw[g * PSTRIDE + nt * 8 + 2 * tg]       = w0;
            *(uint2*)&pw[(g + 8) * PSTRIDE + nt * 8 + 2 * tg] = w1;
        }
        __syncwarp();

#pragma unroll
        for (int kk2 = 0; kk2 < 8; kk2++) {
            uint32_t a0 = pw[g * PSTRIDE + kk2 * 8 + tg];
            uint32_t a1 = pw[(g + 8) * PSTRIDE + kk2 * 8 + tg];
            uint32_t a2 = pw[g * PSTRIDE + kk2 * 8 + tg + 4];
            uint32_t a3 = pw[(g + 8) * PSTRIDE + kk2 * 8 + tg + 4];
#pragma unroll
            for (int nt = 0; nt < 4; nt++) {
                uint32_t b0 = Vs[(kk2 * 8 + tg) * KSTRIDE + nt * 8 + g];
                uint32_t b1 = Vs[(kk2 * 8 + tg + 4) * KSTRIDE + nt * 8 + g];
                mma_tf32(o_[nt][0], o_[nt][1], o_[nt][2], o_[nt][3],
                         a0, a1, a2, a3, b0, b1);
            }
        }
        __syncwarp();
    }

    l0 += __shfl_xor_sync(0xffffffffu, l0, 1);
    l0 += __shfl_xor_sync(0xffffffffu, l0, 2);
    l1 += __shfl_xor_sync(0xffffffffu, l1, 1);
    l1 += __shfl_xor_sync(0xffffffffu, l1, 2);
    const float i0 = 1.f / l0;
    const float i1 = 1.f / l1;

    const int qrow0 = q0 + wid * 16 + g;
    float* y0 = g_y + (size_t)(b * T_ + qrow0) * C_ + h * HD_;
    float* y1 = y0 + (size_t)8 * C_;
#pragma unroll
    for (int nt = 0; nt < 4; nt++) {
        float2 r0; r0.x = o_[nt][0] * i0; r0.y = o_[nt][1] * i0;
        float2 r1; r1.x = o_[nt][2] * i1; r1.y = o_[nt][3] * i1;
        *(float2*)&y0[nt * 8 + 2 * tg] = r0;
        *(float2*)&y1[nt * 8 + 2 * tg] = r1;
    }
}

// ----------------------------------------------------------------------------
extern "C" void kernel_launch(void* const* d_in, const int* in_sizes, int n_in,
                              void* d_out, int out_size)
{
    const float* x      = (const float*)d_in[0];
    const float* w_qkv  = (const float*)d_in[1];
    const float* b_qkv  = (const float*)d_in[2];
    const float* w_proj = (const float*)d_in[3];
    const float* b_proj = (const float*)d_in[4];
    float* out = (float*)d_out;

    float* qkv_ptr = nullptr;
    float* y_ptr   = nullptr;
    cudaGetSymbolAddress((void**)&qkv_ptr, g_qkv);
    cudaGetSymbolAddress((void**)&y_ptr,   g_y);

    const int M = B_ * T_;    // 8192

    // 1) QKV GEMM: [8192,256] @ [256,768] + bias  (tensor cores, 3xTF32)
    {
        dim3 grid(C3_ / 64, M / 128);
        gemm_mma_kernel<<<grid, 256>>>(x, w_qkv, b_qkv, qkv_ptr, M, C3_, C_);
    }

    // 2) Causal attention (tensor cores)
    {
        dim3 grid(T_ / 64, B_ * H_);
        attn_mma_kernel<<<grid, 128>>>();
    }

    // 3) Projection GEMM: [8192,256] @ [256,256] + bias -> d_out
    {
        dim3 grid(C_ / 64, M / 128);
        gemm_mma_kernel<<<grid, 256>>>(y_ptr, w_proj, b_proj, out, M, C_, C_);
    }
}